// round 5
// baseline (speedup 1.0000x reference)
#include <cuda_runtime.h>
#include <cuda_bf16.h>
#include <math_constants.h>

// Problem: N=16384 rows, C=1000 classes, 9 matrices (outputs1..8 + mimic).
// Per row/matrix: margin = (x[target] == top1) ? top1 - top2 : 0
// out_threshold = softmax(margins / 2) per row  -> d_out[1 + row*9 + m]
// max_preds    = max over all elements of matrices 0..7 -> d_out[0]
//
// targets dtype is ambiguous (reference asks int64; JAX x64-off coerces to
// int32). A detect pre-kernel inspects odd 32-bit words: all-zero => int64
// (high halves of values < 1000), any nonzero => int32.

#define C_DIM 1000
#define CHUNKS 250          // C_DIM / 4 float4 chunks
#define BLOCK 256
#define NEG_INF (-CUDART_INF_F)

struct Ptrs { const float* p[9]; };

__device__ unsigned g_max_enc;
__device__ int g_t_is32;

__device__ __forceinline__ unsigned enc_f(float x) {
    unsigned u = __float_as_uint(x);
    return (u & 0x80000000u) ? ~u : (u | 0x80000000u);
}
__device__ __forceinline__ float dec_f(unsigned e) {
    return (e & 0x80000000u) ? __uint_as_float(e ^ 0x80000000u)
                             : __uint_as_float(~e);
}

__global__ void init_kernel() {
    g_max_enc = enc_f(NEG_INF);
}

// Detect int32 vs int64 targets. n32 = N (safe to read N words in both modes).
__global__ void detect_kernel(const unsigned* __restrict__ t32, int n32) {
    __shared__ unsigned s[256];
    unsigned any = 0;
    for (int i = 1 + 2 * (int)threadIdx.x; i < n32; i += 512)
        any |= t32[i];
    s[threadIdx.x] = any;
    __syncthreads();
    for (int o = 128; o > 0; o >>= 1) {
        if (threadIdx.x < (unsigned)o) s[threadIdx.x] |= s[threadIdx.x + o];
        __syncthreads();
    }
    if (threadIdx.x == 0) g_t_is32 = (s[0] != 0) ? 1 : 0;
}

__global__ void finalize_kernel(float* out) {
    out[0] = dec_f(g_max_enc);
}

// merge two (top1, top2) pairs -> (n1, n2)
__device__ __forceinline__ void merge_top2(float& t1, float& t2, float o1, float o2) {
    float n1 = fmaxf(t1, o1);
    float n2 = fmaxf(fminf(t1, o1), fmaxf(t2, o2));
    t1 = n1; t2 = n2;
}

__global__ __launch_bounds__(BLOCK)
void margin_softmax_kernel(Ptrs ptrs, const void* __restrict__ targets_raw,
                           float* __restrict__ out) {
    const int row  = blockIdx.x;
    const int t    = threadIdx.x;
    const int lane = t & 31;
    const int wid  = t >> 5;

    __shared__ float s_t1[9][8];
    __shared__ float s_t2[9][8];
    __shared__ float s_tv[9][8];
    __shared__ float s_gm[8];
    __shared__ float s_margin[9];

    long long tg;
    if (g_t_is32) tg = (long long)((const int*)targets_raw)[row];
    else          tg = ((const long long*)targets_raw)[row];

    const int  tg_chunk = (int)(tg >> 2);
    const int  tg_elem  = (int)(tg & 3);
    const bool active   = (t < CHUNKS);

    // Batch all 9 loads up front: MLP = 9 independent float4 DRAM loads / thread.
    float4 v[9];
#pragma unroll
    for (int m = 0; m < 9; m++) {
        if (active) {
            const float4* rp = reinterpret_cast<const float4*>(
                ptrs.p[m] + (size_t)row * C_DIM);
            v[m] = rp[t];
        } else {
            v[m] = make_float4(NEG_INF, NEG_INF, NEG_INF, NEG_INF);
        }
    }

    float gmax = NEG_INF;

#pragma unroll
    for (int m = 0; m < 9; m++) {
        float a = v[m].x, b = v[m].y, c = v[m].z, d = v[m].w;

        // top-2 of 4 (branchless)
        float hi1 = fmaxf(a, b), lo1 = fminf(a, b);
        float hi2 = fmaxf(c, d), lo2 = fminf(c, d);
        float t1 = fmaxf(hi1, hi2);
        float t2 = fmaxf(fminf(hi1, hi2), (hi1 >= hi2) ? lo1 : lo2);

        // target value (exact element, only on the owning thread)
        float tv = NEG_INF;
        if (active && t == tg_chunk) {
            tv = (tg_elem == 0) ? a : (tg_elem == 1) ? b : (tg_elem == 2) ? c : d;
        }

        if (m < 8) gmax = fmaxf(gmax, fmaxf(fmaxf(a, b), fmaxf(c, d)));

        // warp-level top2 + tv reduction
#pragma unroll
        for (int off = 16; off > 0; off >>= 1) {
            float o1 = __shfl_down_sync(0xFFFFFFFFu, t1, off);
            float o2 = __shfl_down_sync(0xFFFFFFFFu, t2, off);
            float ov = __shfl_down_sync(0xFFFFFFFFu, tv, off);
            merge_top2(t1, t2, o1, o2);
            tv = fmaxf(tv, ov);
        }
        if (lane == 0) {
            s_t1[m][wid] = t1;
            s_t2[m][wid] = t2;
            s_tv[m][wid] = tv;
        }
    }

    // warp-level gmax reduction
#pragma unroll
    for (int off = 16; off > 0; off >>= 1)
        gmax = fmaxf(gmax, __shfl_down_sync(0xFFFFFFFFu, gmax, off));
    if (lane == 0) s_gm[wid] = gmax;

    __syncthreads();

    if (wid == 0) {
        // global max across 8 warps
        float g = (lane < 8) ? s_gm[lane] : NEG_INF;
#pragma unroll
        for (int off = 4; off > 0; off >>= 1)
            g = fmaxf(g, __shfl_down_sync(0xFFFFFFFFu, g, off));
        if (lane == 0) atomicMax(&g_max_enc, enc_f(g));

        // per-matrix final reduce across 8 warps
#pragma unroll
        for (int m = 0; m < 9; m++) {
            float t1 = (lane < 8) ? s_t1[m][lane] : NEG_INF;
            float t2 = (lane < 8) ? s_t2[m][lane] : NEG_INF;
            float tv = (lane < 8) ? s_tv[m][lane] : NEG_INF;
#pragma unroll
            for (int off = 4; off > 0; off >>= 1) {
                float o1 = __shfl_down_sync(0xFFFFFFFFu, t1, off);
                float o2 = __shfl_down_sync(0xFFFFFFFFu, t2, off);
                float ov = __shfl_down_sync(0xFFFFFFFFu, tv, off);
                merge_top2(t1, t2, o1, o2);
                tv = fmaxf(tv, ov);
            }
            if (lane == 0)
                s_margin[m] = (tv == t1) ? (t1 - t2) : 0.0f;
        }
    }

    __syncthreads();

    if (t == 0) {
        float mm = s_margin[0];
#pragma unroll
        for (int m = 1; m < 9; m++) mm = fmaxf(mm, s_margin[m]);
        float e[9];
        float sum = 0.0f;
#pragma unroll
        for (int m = 0; m < 9; m++) {
            e[m] = __expf((s_margin[m] - mm) * 0.5f);
            sum += e[m];
        }
        float inv = 1.0f / sum;
        float* orow = out + 1 + (size_t)row * 9;
#pragma unroll
        for (int m = 0; m < 9; m++) orow[m] = e[m] * inv;
    }
}

extern "C" void kernel_launch(void* const* d_in, const int* in_sizes, int n_in,
                              void* d_out, int out_size) {
    Ptrs ps;
    for (int i = 0; i < 9; i++) ps.p[i] = (const float*)d_in[i];
    const void* targets = d_in[9];
    float* out = (float*)d_out;

    const int N = in_sizes[9];   // targets element count = 16384

    init_kernel<<<1, 1>>>();
    detect_kernel<<<1, 256>>>((const unsigned*)targets, N);
    margin_softmax_kernel<<<N, BLOCK>>>(ps, targets, out);
    finalize_kernel<<<1, 1>>>(out);
}

// round 6
// speedup vs baseline: 1.1422x; 1.1422x over previous
#include <cuda_runtime.h>
#include <cuda_bf16.h>
#include <math_constants.h>

// N=16384 rows, C=1000 classes, 9 matrices (outputs1..8 + mimic).
// Per row/matrix: margin = (x[target] == top1) ? top1 - top2 : 0
// out_threshold = softmax(margins / 2) per row -> d_out[1 + row*9 + m]
// max_preds = max over all elements of matrices 0..7 -> d_out[0]
//
// Decomposition: 1 block per row, 9 warps per block, warp m owns matrix m.
// Scalar max finalized by the last block (atomic counter pattern).
// targets dtype (int32 vs int64) detected from odd 32-bit words.

#define C_DIM  1000
#define CHUNKS 250          // C_DIM / 4 float4 chunks per row
#define BLOCK  288          // 9 warps
#define NEG_INF (-CUDART_INF_F)

struct Ptrs { const float* p[9]; };

__device__ unsigned g_max_enc;
__device__ unsigned g_done;
__device__ int      g_t_is32;

__device__ __forceinline__ unsigned enc_f(float x) {
    unsigned u = __float_as_uint(x);
    return (u & 0x80000000u) ? ~u : (u | 0x80000000u);
}
__device__ __forceinline__ float dec_f(unsigned e) {
    return (e & 0x80000000u) ? __uint_as_float(e ^ 0x80000000u)
                             : __uint_as_float(~e);
}

// Init scratch + detect targets dtype in one tiny kernel.
// int64 targets in [0,1000) => all odd 32-bit words are 0.
// int32 targets => odd words are random labels, nonzero w.p. 0.999 each.
__global__ void init_detect_kernel(const unsigned* __restrict__ t32, int n32) {
    __shared__ unsigned s[256];
    unsigned any = 0;
    // sample up to 512 odd words
    for (int i = 1 + 2 * (int)threadIdx.x; i < n32 && i < 1024; i += 512)
        any |= t32[i];
    s[threadIdx.x] = any;
    __syncthreads();
    for (int o = 128; o > 0; o >>= 1) {
        if (threadIdx.x < (unsigned)o) s[threadIdx.x] |= s[threadIdx.x + o];
        __syncthreads();
    }
    if (threadIdx.x == 0) {
        g_t_is32  = (s[0] != 0) ? 1 : 0;
        g_max_enc = enc_f(NEG_INF);
        g_done    = 0u;
    }
}

// merge two (top1, top2) pairs
__device__ __forceinline__ void merge_top2(float& t1, float& t2, float o1, float o2) {
    float n1 = fmaxf(t1, o1);
    float n2 = fmaxf(fminf(t1, o1), fmaxf(t2, o2));
    t1 = n1; t2 = n2;
}

__global__ __launch_bounds__(BLOCK)
void margin_softmax_kernel(Ptrs ptrs, const void* __restrict__ targets_raw,
                           float* __restrict__ out) {
    const int row  = blockIdx.x;
    const int t    = threadIdx.x;
    const int lane = t & 31;
    const int w    = t >> 5;          // warp index == matrix index 0..8

    __shared__ float s_margin[9];
    __shared__ float s_gm[8];

    long long tg;
    if (g_t_is32) tg = (long long)((const int*)targets_raw)[row];
    else          tg = ((const long long*)targets_raw)[row];
    const int tg_chunk = (int)(tg >> 2);
    const int tg_elem  = (int)(tg & 3);

    const float4* rp = reinterpret_cast<const float4*>(
        ptrs.p[w] + (size_t)row * C_DIM);

    // 8 independent float4 loads per lane (lane + 32k < 250)
    float4 v[8];
#pragma unroll
    for (int k = 0; k < 8; k++) {
        int c = lane + (k << 5);
        if (c < CHUNKS) v[k] = rp[c];
        else            v[k] = make_float4(NEG_INF, NEG_INF, NEG_INF, NEG_INF);
    }

    float t1 = NEG_INF, t2 = NEG_INF, tv = NEG_INF, gm = NEG_INF;
#pragma unroll
    for (int k = 0; k < 8; k++) {
        float a = v[k].x, b = v[k].y, c = v[k].z, d = v[k].w;
        float hi1 = fmaxf(a, b), lo1 = fminf(a, b);
        float hi2 = fmaxf(c, d), lo2 = fminf(c, d);
        float m1 = fmaxf(hi1, hi2);
        float m2 = fmaxf(fminf(hi1, hi2), (hi1 >= hi2) ? lo1 : lo2);
        merge_top2(t1, t2, m1, m2);
        gm = fmaxf(gm, m1);
        if ((lane + (k << 5)) == tg_chunk)
            tv = (tg_elem == 0) ? a : (tg_elem == 1) ? b : (tg_elem == 2) ? c : d;
    }

    // single warp-level reduction (top2 + tv + gmax together)
#pragma unroll
    for (int off = 16; off > 0; off >>= 1) {
        float o1 = __shfl_down_sync(0xFFFFFFFFu, t1, off);
        float o2 = __shfl_down_sync(0xFFFFFFFFu, t2, off);
        float ov = __shfl_down_sync(0xFFFFFFFFu, tv, off);
        float og = __shfl_down_sync(0xFFFFFFFFu, gm, off);
        merge_top2(t1, t2, o1, o2);
        tv = fmaxf(tv, ov);
        gm = fmaxf(gm, og);
    }
    if (lane == 0) {
        s_margin[w] = (tv == t1) ? (t1 - t2) : 0.0f;
        if (w < 8) s_gm[w] = gm;
    }
    __syncthreads();

    if (t == 0) {
        // block max over the 8 output matrices -> one atomic per block
        float g = s_gm[0];
#pragma unroll
        for (int i = 1; i < 8; i++) g = fmaxf(g, s_gm[i]);
        atomicMax(&g_max_enc, enc_f(g));

        // softmax over 9 margins / T=2
        float mm = s_margin[0];
#pragma unroll
        for (int m = 1; m < 9; m++) mm = fmaxf(mm, s_margin[m]);
        float e[9];
        float sum = 0.0f;
#pragma unroll
        for (int m = 0; m < 9; m++) {
            e[m] = __expf((s_margin[m] - mm) * 0.5f);
            sum += e[m];
        }
        float inv = 1.0f / sum;
        float* orow = out + 1 + (size_t)row * 9;
#pragma unroll
        for (int m = 0; m < 9; m++) orow[m] = e[m] * inv;

        // last block writes the scalar (order-independent => deterministic)
        __threadfence();
        unsigned done = atomicAdd(&g_done, 1u);
        if (done == gridDim.x - 1) {
            unsigned cur = atomicMax(&g_max_enc, 0u);  // atomic read
            out[0] = dec_f(cur);
        }
    }
}

extern "C" void kernel_launch(void* const* d_in, const int* in_sizes, int n_in,
                              void* d_out, int out_size) {
    Ptrs ps;
    for (int i = 0; i < 9; i++) ps.p[i] = (const float*)d_in[i];
    const void* targets = d_in[9];
    float* out = (float*)d_out;

    const int N = in_sizes[9];   // 16384 rows

    init_detect_kernel<<<1, 256>>>((const unsigned*)targets, N);
    margin_softmax_kernel<<<N, BLOCK>>>(ps, targets, out);
}

// round 7
// speedup vs baseline: 1.1991x; 1.0498x over previous
#include <cuda_runtime.h>
#include <cuda_bf16.h>
#include <math_constants.h>

// N=16384 rows, C=1000 classes, 9 matrices (outputs1..8 + mimic).
// Per row/matrix: margin = (x[target] == top1) ? top1 - top2 : 0
// out_threshold = softmax(margins / 2) per row -> d_out[1 + row*9 + m]
// max_preds = max over all elements of matrices 0..7 -> d_out[0]
//
// Single-kernel design: 1 block/row, 9 warps/block, warp m owns matrix m.
//  - gmax == top1 (row max), no separate stream
//  - target value loaded directly (x[row*C+tg]), no scan stream
//  - per-warp dtype detect (int32 vs int64) via REDUX.OR of 32 odd words
//  - scalar finalize + scratch reset done by the last block (graph-replay safe)

#define C_DIM  1000
#define CHUNKS 250          // C_DIM / 4 float4 chunks per row
#define BLOCK  288          // 9 warps
#define NEG_INF (-CUDART_INF_F)
#define ENC_NEG_INF 0x007FFFFFu   // enc_f(-inf)

struct Ptrs { const float* p[9]; };

__device__ unsigned g_max_enc = ENC_NEG_INF;
__device__ unsigned g_done    = 0u;

__device__ __forceinline__ unsigned enc_f(float x) {
    unsigned u = __float_as_uint(x);
    return (u & 0x80000000u) ? ~u : (u | 0x80000000u);
}
__device__ __forceinline__ float dec_f(unsigned e) {
    return (e & 0x80000000u) ? __uint_as_float(e ^ 0x80000000u)
                             : __uint_as_float(~e);
}

// accumulate top-2 of a float4 into (t1, t2)
__device__ __forceinline__ void acc4(float4 v, float& t1, float& t2) {
    float hi1 = fmaxf(v.x, v.y), lo1 = fminf(v.x, v.y);
    float hi2 = fmaxf(v.z, v.w), lo2 = fminf(v.z, v.w);
    float m1 = fmaxf(hi1, hi2);
    float m2 = fmaxf(fminf(hi1, hi2), (hi1 >= hi2) ? lo1 : lo2);
    t2 = fmaxf(fminf(t1, m1), fmaxf(t2, m2));
    t1 = fmaxf(t1, m1);
}

__global__ __launch_bounds__(BLOCK, 6)
void margin_softmax_kernel(Ptrs ptrs, const unsigned* __restrict__ t32,
                           float* __restrict__ out) {
    const int row  = blockIdx.x;
    const int t    = threadIdx.x;
    const int lane = t & 31;
    const int w    = t >> 5;          // warp index == matrix index 0..8

    __shared__ float s_margin[9];
    __shared__ float s_gm[8];

    const float* rowp = ptrs.p[w] + (size_t)row * C_DIM;

    // ---- wave A: chunks lane + {0,32,64,96} (always in range) ----
    const float4* rp4 = reinterpret_cast<const float4*>(rowp);
    float4 va0 = rp4[lane];
    float4 va1 = rp4[lane + 32];
    float4 va2 = rp4[lane + 64];
    float4 va3 = rp4[lane + 96];

    // per-warp targets dtype detect: int64 values <1000 => all odd words 0
    unsigned odd = t32[2 * lane + 1];
    unsigned is32 = __reduce_or_sync(0xFFFFFFFFu, odd);
    long long tg;
    if (is32) tg = (long long)((const int*)t32)[row];
    else      tg = ((const long long*)t32)[row];

    // direct target-value load (uniform address -> broadcast sector)
    float tv = rowp[tg];

    float t1 = NEG_INF, t2 = NEG_INF;
    acc4(va0, t1, t2);
    acc4(va1, t1, t2);
    acc4(va2, t1, t2);
    acc4(va3, t1, t2);

    // ---- wave B: chunks lane + {128,160,192,224} (last predicated) ----
    float4 vb0 = rp4[lane + 128];
    float4 vb1 = rp4[lane + 160];
    float4 vb2 = rp4[lane + 192];
    float4 vb3 = (lane + 224 < CHUNKS) ? rp4[lane + 224]
               : make_float4(NEG_INF, NEG_INF, NEG_INF, NEG_INF);
    acc4(vb0, t1, t2);
    acc4(vb1, t1, t2);
    acc4(vb2, t1, t2);
    acc4(vb3, t1, t2);

    // warp top-2 reduction (2 streams only)
#pragma unroll
    for (int off = 16; off > 0; off >>= 1) {
        float o1 = __shfl_down_sync(0xFFFFFFFFu, t1, off);
        float o2 = __shfl_down_sync(0xFFFFFFFFu, t2, off);
        t2 = fmaxf(fminf(t1, o1), fmaxf(t2, o2));
        t1 = fmaxf(t1, o1);
    }
    if (lane == 0) {
        s_margin[w] = (tv == t1) ? (t1 - t2) : 0.0f;
        if (w < 8) s_gm[w] = t1;   // gmax == top1 of the row for matrix w
    }
    __syncthreads();

    if (w == 0) {
        // softmax over 9 margins / T=2, parallel in lanes 0..8 (16-lane butterfly)
        float m = (lane < 9) ? s_margin[lane] : NEG_INF;
        float mm = m;
#pragma unroll
        for (int off = 8; off > 0; off >>= 1)
            mm = fmaxf(mm, __shfl_xor_sync(0xFFFFFFFFu, mm, off, 16));
        float e = __expf((m - mm) * 0.5f);
        float sum = e;
#pragma unroll
        for (int off = 8; off > 0; off >>= 1)
            sum += __shfl_xor_sync(0xFFFFFFFFu, sum, off, 16);
        if (lane < 9)
            out[1 + (size_t)row * 9 + lane] = __fdividef(e, sum);
    } else if (w == 1 && lane == 0) {
        // scalar max path + last-block finalize
        float g = s_gm[0];
#pragma unroll
        for (int i = 1; i < 8; i++) g = fmaxf(g, s_gm[i]);
        atomicMax(&g_max_enc, enc_f(g));
        __threadfence();
        unsigned done = atomicAdd(&g_done, 1u);
        if (done == gridDim.x - 1) {
            __threadfence();
            unsigned cur = atomicOr(&g_max_enc, 0u);   // atomic read
            out[0] = dec_f(cur);
            // reset scratch for the next graph replay
            g_max_enc = ENC_NEG_INF;
            g_done    = 0u;
        }
    }
}

extern "C" void kernel_launch(void* const* d_in, const int* in_sizes, int n_in,
                              void* d_out, int out_size) {
    Ptrs ps;
    for (int i = 0; i < 9; i++) ps.p[i] = (const float*)d_in[i];
    const unsigned* targets = (const unsigned*)d_in[9];
    float* out = (float*)d_out;

    const int N = in_sizes[9];   // 16384 rows

    margin_softmax_kernel<<<N, BLOCK>>>(ps, targets, out);
}

// round 8
// speedup vs baseline: 1.3407x; 1.1181x over previous
#include <cuda_runtime.h>
#include <cuda_bf16.h>
#include <math_constants.h>

// N=16384 rows, C=1000 classes, 9 matrices (outputs1..8 + mimic).
// Per row/matrix: margin = (x[target] == top1) ? top1 - top2 : 0
// out_threshold = softmax(margins / 2) per row -> d_out[1 + row*9 + m]
// max_preds = max over all elements of matrices 0..7 -> d_out[0]
//
// Persistent single-kernel design: grid ~= SMs*6 blocks, 9 warps/block,
// warp m owns matrix m; each block grid-strides over rows (n_waves = 1).
//  - gmax == top1, accumulated in-register across rows, 1 atomic per block
//  - target value loaded directly; dtype detect hoisted (REDUX.OR, once)
//  - double-buffered s_margin -> one __syncthreads per row
//  - last block finalizes scalar + resets scratch (graph-replay safe)

#define C_DIM  1000
#define CHUNKS 250          // C_DIM / 4 float4 chunks per row
#define BLOCK  288          // 9 warps
#define NEG_INF (-CUDART_INF_F)
#define ENC_NEG_INF 0x007FFFFFu   // enc_f(-inf)

struct Ptrs { const float* p[9]; };

__device__ unsigned g_max_enc = ENC_NEG_INF;
__device__ unsigned g_done    = 0u;

__device__ __forceinline__ unsigned enc_f(float x) {
    unsigned u = __float_as_uint(x);
    return (u & 0x80000000u) ? ~u : (u | 0x80000000u);
}
__device__ __forceinline__ float dec_f(unsigned e) {
    return (e & 0x80000000u) ? __uint_as_float(e ^ 0x80000000u)
                             : __uint_as_float(~e);
}

// accumulate top-2 of a float4 into (t1, t2)
__device__ __forceinline__ void acc4(float4 v, float& t1, float& t2) {
    float hi1 = fmaxf(v.x, v.y), lo1 = fminf(v.x, v.y);
    float hi2 = fmaxf(v.z, v.w), lo2 = fminf(v.z, v.w);
    float m1 = fmaxf(hi1, hi2);
    float m2 = fmaxf(fminf(hi1, hi2), (hi1 >= hi2) ? lo1 : lo2);
    t2 = fmaxf(fminf(t1, m1), fmaxf(t2, m2));
    t1 = fmaxf(t1, m1);
}

__global__ __launch_bounds__(BLOCK, 6)
void margin_softmax_kernel(Ptrs ptrs, const unsigned* __restrict__ t32,
                           float* __restrict__ out, int nrows) {
    const int t    = threadIdx.x;
    const int lane = t & 31;
    const int w    = t >> 5;          // warp index == matrix index 0..8

    __shared__ float s_margin[2][12]; // double-buffered, padded
    __shared__ float s_gm[8];

    // targets dtype detect, once: int64 values < 1000 => all odd words 0
    unsigned odd  = t32[2 * lane + 1];
    unsigned is32 = __reduce_or_sync(0xFFFFFFFFu, odd);

    const float* base = ptrs.p[w];
    float gm = NEG_INF;               // per-warp running max (lane 0 authoritative)

    int it = 0;
    for (int row = blockIdx.x; row < nrows; row += gridDim.x, ++it) {
        long long tg;
        if (is32) tg = (long long)((const int*)t32)[row];
        else      tg = ((const long long*)t32)[row];

        const float* rowp = base + (size_t)row * C_DIM;
        const float4* rp4 = reinterpret_cast<const float4*>(rowp);

        float tv = rowp[tg];          // broadcast load (uniform in warp)

        // wave A: chunks lane + {0,32,64,96}
        float4 va0 = rp4[lane];
        float4 va1 = rp4[lane + 32];
        float4 va2 = rp4[lane + 64];
        float4 va3 = rp4[lane + 96];
        float t1 = NEG_INF, t2 = NEG_INF;
        acc4(va0, t1, t2);
        acc4(va1, t1, t2);
        acc4(va2, t1, t2);
        acc4(va3, t1, t2);

        // wave B: chunks lane + {128,160,192,224} (last predicated)
        float4 vb0 = rp4[lane + 128];
        float4 vb1 = rp4[lane + 160];
        float4 vb2 = rp4[lane + 192];
        float4 vb3 = (lane + 224 < CHUNKS) ? rp4[lane + 224]
                   : make_float4(NEG_INF, NEG_INF, NEG_INF, NEG_INF);
        acc4(vb0, t1, t2);
        acc4(vb1, t1, t2);
        acc4(vb2, t1, t2);
        acc4(vb3, t1, t2);

        // warp top-2 reduction
#pragma unroll
        for (int off = 16; off > 0; off >>= 1) {
            float o1 = __shfl_down_sync(0xFFFFFFFFu, t1, off);
            float o2 = __shfl_down_sync(0xFFFFFFFFu, t2, off);
            t2 = fmaxf(fminf(t1, o1), fmaxf(t2, o2));
            t1 = fmaxf(t1, o1);
        }
        if (lane == 0) {
            s_margin[it & 1][w] = (tv == t1) ? (t1 - t2) : 0.0f;
            gm = fmaxf(gm, t1);       // row max == top1
        }
        __syncthreads();

        if (w == 0) {
            // softmax over 9 margins / T=2, lanes 0..8 (16-lane butterfly)
            float m = (lane < 9) ? s_margin[it & 1][lane] : NEG_INF;
            float mm = m;
#pragma unroll
            for (int off = 8; off > 0; off >>= 1)
                mm = fmaxf(mm, __shfl_xor_sync(0xFFFFFFFFu, mm, off, 16));
            float e = __expf((m - mm) * 0.5f);
            float sum = e;
#pragma unroll
            for (int off = 8; off > 0; off >>= 1)
                sum += __shfl_xor_sync(0xFFFFFFFFu, sum, off, 16);
            if (lane < 9)
                out[1 + (size_t)row * 9 + lane] = __fdividef(e, sum);
        }
        // s_margin WAR across iterations is protected by double buffering:
        // buffer (it&1) is rewritten only after two more barriers.
    }

    // block-level scalar max: one shared write per warp, one atomic per block
    if (lane == 0 && w < 8) s_gm[w] = gm;
    __syncthreads();
    if (t == 0) {
        float g = s_gm[0];
#pragma unroll
        for (int i = 1; i < 8; i++) g = fmaxf(g, s_gm[i]);
        atomicMax(&g_max_enc, enc_f(g));
        __threadfence();
        unsigned done = atomicAdd(&g_done, 1u);
        if (done == gridDim.x - 1) {
            __threadfence();
            unsigned cur = atomicOr(&g_max_enc, 0u);   // atomic read
            out[0] = dec_f(cur);
            // reset scratch for next graph replay
            g_max_enc = ENC_NEG_INF;
            g_done    = 0u;
        }
    }
}

extern "C" void kernel_launch(void* const* d_in, const int* in_sizes, int n_in,
                              void* d_out, int out_size) {
    Ptrs ps;
    for (int i = 0; i < 9; i++) ps.p[i] = (const float*)d_in[i];
    const unsigned* targets = (const unsigned*)d_in[9];
    float* out = (float*)d_out;

    const int N = in_sizes[9];   // 16384 rows

    int sms = 148;
    cudaDeviceGetAttribute(&sms, cudaDevAttrMultiProcessorCount, 0);
    int grid = sms * 6;
    if (grid > N) grid = N;

    margin_softmax_kernel<<<grid, BLOCK>>>(ps, targets, out, N);
}